// round 11
// baseline (speedup 1.0000x reference)
#include <cuda_runtime.h>
#include <cuda_fp16.h>
#include <math.h>
#include <stdint.h>

// Problem constants
#define BATCH 1024
#define TT    256
#define FF    128
#define HH    256
#define GG    1024   // 4*H
#define OO    50

// ---------------------------------------------------------------------------
// Static device scratch (allocation-free per harness rules)
// NOTE R9 bug fixed here: W images are 640 uint4 PER CHUNK (64 rows x 40
// halves x hi+lo = 10240 B); R9 declared 320 and overflowed into the barrier
// words -> deadlock.
// ---------------------------------------------------------------------------
__device__ __align__(16) __half g_xh[(size_t)TT * BATCH * FF];   // x split hi, [t][b][f]
__device__ __align__(16) __half g_xl[(size_t)TT * BATCH * FF];   // x split lo
__device__ __align__(16) __half g_h0h[(size_t)TT * BATCH * HH];  // layer-0 h seq, hi
__device__ __align__(16) __half g_h0l[(size_t)TT * BATCH * HH];  // layer-0 h seq, lo
__device__ __align__(16) __half g_hbh[2][BATCH * HH];            // h state hi, dbl-buf
__device__ __align__(16) __half g_hbl[2][BATCH * HH];            // h state lo
__device__ uint4 g_w0p[16 * 4 * 640];   // W0 pre-split chunk images (10240 B/chunk)
__device__ uint4 g_w1p[16 * 8 * 640];   // W1 pre-split chunk images
__device__ unsigned g_barleaf[16 * 32];
__device__ unsigned g_barroot = 0;
__device__ unsigned g_bargen = 0;

// ---------------------------------------------------------------------------
// Two-level grid barrier (proven R7/R8)
// ---------------------------------------------------------------------------
__device__ __forceinline__ void gbar() {
    __syncthreads();
    if (threadIdx.x == 0) {
        __threadfence();
        unsigned gen = *((volatile unsigned*)&g_bargen);
        unsigned* leaf = &g_barleaf[(blockIdx.x & 15) * 32];
        if (atomicAdd(leaf, 1) == 15) {
            atomicExch(leaf, 0);
            if (atomicAdd(&g_barroot, 1) == 15) {
                atomicExch(&g_barroot, 0);
                __threadfence();
                atomicExch(&g_bargen, gen + 1);
            } else {
                while (*((volatile unsigned*)&g_bargen) == gen) { __nanosleep(16); }
            }
        } else {
            while (*((volatile unsigned*)&g_bargen) == gen) { __nanosleep(16); }
        }
        __threadfence();
    }
    __syncthreads();
}

__device__ __forceinline__ float sigf(float x) { return 1.0f / (1.0f + expf(-x)); }

// ---------------------------------------------------------------------------
// fp16 mma.sync m16n8k16 (f32 accumulate) + ldmatrix helpers
// ---------------------------------------------------------------------------
__device__ __forceinline__ void mma_f16(float* c, const unsigned* a, const unsigned* b) {
    asm volatile(
        "mma.sync.aligned.m16n8k16.row.col.f32.f16.f16.f32 "
        "{%0,%1,%2,%3}, {%4,%5,%6,%7}, {%8,%9}, {%0,%1,%2,%3};"
        : "+f"(c[0]), "+f"(c[1]), "+f"(c[2]), "+f"(c[3])
        : "r"(a[0]), "r"(a[1]), "r"(a[2]), "r"(a[3]), "r"(b[0]), "r"(b[1]));
}
__device__ __forceinline__ void ldsm_x4(unsigned* r, uint32_t addr) {
    asm volatile("ldmatrix.sync.aligned.m8n8.x4.shared.b16 {%0,%1,%2,%3}, [%4];"
        : "=r"(r[0]), "=r"(r[1]), "=r"(r[2]), "=r"(r[3]) : "r"(addr));
}
__device__ __forceinline__ uint32_t smem_u32(const void* p) {
    uint32_t a;
    asm("{ .reg .u64 t; cvta.to.shared.u64 t, %1; cvt.u32.u64 %0, t; }"
        : "=r"(a) : "l"(p));
    return a;
}

// split fp32 -> fp16 hi + fp16 lo (hi+lo carries ~22 significand bits)
__device__ __forceinline__ void splith(float f, __half& h, __half& l) {
    h = __float2half_rn(f);
    l = __float2half_rn(f - __half2float(h));
}
__device__ __forceinline__ void split2(float a, float b, unsigned& h, unsigned& l) {
    __half2 h2 = __floats2half2_rn(a, b);
    float ra = a - __low2float(h2);
    float rb = b - __high2float(h2);
    __half2 l2 = __floats2half2_rn(ra, rb);
    h = *(unsigned*)&h2;
    l = *(unsigned*)&l2;
}

// ---------------------------------------------------------------------------
// Prep: split x [B][T][F] fp32 -> [t][b][f] fp16 hi/lo planes (half2 grain)
// ---------------------------------------------------------------------------
__global__ __launch_bounds__(256) void split_x_kernel(const float* __restrict__ x) {
    size_t idx = (size_t)blockIdx.x * 256 + threadIdx.x;  // over T*B*F/2
    int f2 = (int)(idx & 63);
    int b  = (int)((idx >> 6) & 1023);
    int t  = (int)(idx >> 16);
    float2 v = *(const float2*)(x + ((size_t)b * TT + t) * FF + f2 * 2);
    unsigned h, l;
    split2(v.x, v.y, h, l);
    size_t o = ((size_t)t * BATCH + b) * FF + f2 * 2;
    *(unsigned*)(g_xh + o) = h;
    *(unsigned*)(g_xl + o) = l;
}

// ---------------------------------------------------------------------------
// Prep: split + permute W [K][1024] fp32 into per-hj ldmatrix-ready chunk
// images: out[(hj*(K/32)+c)*5120 + n*40 + kk] (hi), +2560 (lo), in halves.
// n = (hl>>3)*32 + gate*8 + (hl&7)  — matches rec's resident-U col order.
// ---------------------------------------------------------------------------
__global__ __launch_bounds__(256) void split_w_kernel(const float* __restrict__ W,
                                                      int K, __half* __restrict__ out) {
    int idx = blockIdx.x * 256 + threadIdx.x;   // over K*1024
    if (idx >= K * 1024) return;
    int k = idx >> 10, gcol = idx & 1023;
    int gate = gcol >> 8;
    int h16  = gcol & 255;
    int hj = h16 >> 4, hl = h16 & 15;
    int n = (hl >> 3) * 32 + gate * 8 + (hl & 7);
    int c = k >> 5, kk = k & 31;
    float v = W[(size_t)k * GG + gcol];
    __half hb, lb;
    splith(v, hb, lb);
    size_t base = ((size_t)(hj * (K / 32) + c)) * 5120 + n * 40 + kk;
    out[base] = hb;
    out[base + 2560] = lb;
}

// ---------------------------------------------------------------------------
// Fused persistent LSTM layer: z = [h_{t-1}, A[t]] @ [U; W] + bias.
// 256 blocks (16 batch x 16 h chunks), 256 thr = 8 warps (4M x 2N).
// U resident in SMEM; W chunks streamed pre-split from L2; A = x (layer0,
// AK=128) or h0seq (layer1, AK=256) as pre-split fp16 planes.
// SMEM map (bytes): Uh 0, Ul 33792, A-staging 67584..88064 (2 buf),
//                   W-staging 88064..108544 (2 buf x [hi 5120 | lo 5120]).
// ---------------------------------------------------------------------------
template<int AK>
__global__ __launch_bounds__(256, 2) void lstm_fused(
    const __half* __restrict__ Aph, const __half* __restrict__ Apl, // [T][B][AK]
    const uint4*  __restrict__ Wp,   // pre-permuted W chunk images
    const float*  __restrict__ U,    // [H][G] fp32
    const float*  __restrict__ bias, // [G] fp32
    __half* __restrict__ seqH, __half* __restrict__ seqL)
{
    constexpr int NC = 8 + AK / 32;       // total k-chunks (U part + A part)
    extern __shared__ __align__(16) unsigned smw[];
    unsigned* HhB[2] = {smw + 16896, smw + 19456};
    unsigned* HlB[2] = {smw + 18176, smw + 20736};
    __half* UhE = (__half*)smw;
    __half* UlE = (__half*)(smw + 8448);

    const int tid  = threadIdx.x;
    const int lane = tid & 31;
    const int w    = tid >> 5;
    const int wm   = w & 3, wn = w >> 2;
    const int trow = lane >> 2, q = lane & 3;
    const int bi   = blockIdx.x >> 4;
    const int hj   = blockIdx.x & 15;

    // ---- load + split U slice (resident, gate-permuted)
    for (int idx = tid; idx < 64 * 256; idx += 256) {
        int n = idx & 63, k = idx >> 6;
        int gcol = ((n >> 3) & 3) * HH + hj * 16 + (n >> 5) * 8 + (n & 7);
        float v = U[(size_t)k * GG + gcol];
        __half hb, lb;
        splith(v, hb, lb);
        UhE[n * 264 + k] = hb;
        UlE[n * 264 + k] = lb;
    }
    // ---- zero h-state buffer 0 (this block's cols)
    {
        int r = tid >> 2, c0 = (tid & 3) * 4;
        uint2 z = make_uint2(0u, 0u);
        *(uint2*)&g_hbh[0][(size_t)(bi * 64 + r) * HH + hj * 16 + c0] = z;
        *(uint2*)&g_hbl[0][(size_t)(bi * 64 + r) * HH + hj * 16 + c0] = z;
    }
    gbar();

    const uint32_t usm = smem_u32(smw);
    const uint32_t hhOff[2] = {67584u, 77824u};
    const uint32_t hlOff[2] = {72704u, 82944u};
    const uint32_t aofs  = (uint32_t)(wm * 16 + (lane & 15)) * 80 + ((lane >> 4) & 1) * 16;
    const uint32_t bofsU = (uint32_t)(wn * 32 + ((lane >> 4) & 1) * 8 + (lane & 7)) * 528
                         + ((lane >> 3) & 1) * 16;
    const uint32_t bofsW = (uint32_t)(wn * 32 + ((lane >> 4) & 1) * 8 + (lane & 7)) * 80
                         + ((lane >> 3) & 1) * 16;

    const int hcol0 = hj * 16 + wn * 8 + 2 * q;
    const int srow  = tid >> 2;
    const int skw   = (tid & 3) * 4;      // staging k offset (u32 words)
    const int skw2  = skw * 2;            // in halves

    // bias registers: br[g][pp]
    float br[4][2];
#pragma unroll
    for (int g = 0; g < 4; ++g) {
        br[g][0] = bias[g * 256 + hcol0];
        br[g][1] = bias[g * 256 + hcol0 + 1];
    }

    float cst[4] = {0.f, 0.f, 0.f, 0.f};

    for (int t = 0; t < TT; ++t) {
        const __half* hinH = g_hbh[t & 1];
        const __half* hinL = g_hbl[t & 1];
        __half* houtH = g_hbh[(t + 1) & 1];
        __half* houtL = g_hbl[(t + 1) & 1];

        const __half* hrowH = hinH + (size_t)(bi * 64 + srow) * HH;
        const __half* hrowL = hinL + (size_t)(bi * 64 + srow) * HH;
        const __half* arowH = Aph + ((size_t)t * BATCH + bi * 64 + srow) * AK;
        const __half* arowL = Apl + ((size_t)t * BATCH + bi * 64 + srow) * AK;

        uint4 ph = *(const uint4*)(hrowH + skw2);
        uint4 pl = *(const uint4*)(hrowL + skw2);

        float acc[4][4];
#pragma unroll
        for (int g = 0; g < 4; ++g)
#pragma unroll
            for (int r = 0; r < 4; ++r) acc[g][r] = 0.0f;

        for (int c = 0; c < NC; ++c) {
            const int cb = c & 1;
            // stage A chunk c
            *(uint4*)&HhB[cb][srow * 20 + skw] = ph;
            *(uint4*)&HlB[cb][srow * 20 + skw] = pl;

            const int cn = c + 1;
            // prefetch A chunk c+1
            if (cn < NC) {
                const __half *sH, *sL;
                if (cn < 8) { sH = hrowH + cn * 32 + skw2;        sL = hrowL + cn * 32 + skw2; }
                else        { sH = arowH + (cn - 8) * 32 + skw2;  sL = arowL + (cn - 8) * 32 + skw2; }
                ph = *(const uint4*)sH;
                pl = *(const uint4*)sL;
            }
            // prefetch W chunk c+1 (L2) into registers
            uint4 w0v, w1v, w2v;
            const bool wld = (cn >= 8) && (cn < NC);
            if (wld) {
                const uint4* ws = Wp + ((size_t)hj * (AK / 32) + (cn - 8)) * 640;
                w0v = ws[tid];
                w1v = ws[tid + 256];
                if (tid < 128) w2v = ws[tid + 512];
            }
            __syncthreads();

            // compute chunk c
#pragma unroll
            for (int s = 0; s < 2; ++s) {
                unsigned ah[4], al[4];
                ldsm_x4(ah, usm + hhOff[cb] + aofs + s * 32);
                ldsm_x4(al, usm + hlOff[cb] + aofs + s * 32);
#pragma unroll
                for (int gp = 0; gp < 2; ++gp) {
                    unsigned bh4[4], bl4[4];
                    if (c < 8) {
                        uint32_t ub = usm + bofsU + gp * 8448 + c * 64 + s * 32;
                        ldsm_x4(bh4, ub);
                        ldsm_x4(bl4, ub + 33792u);
                    } else {
                        uint32_t wb = usm + 88064u + (uint32_t)cb * 10240u
                                    + bofsW + gp * 1280 + s * 32;
                        ldsm_x4(bh4, wb);
                        ldsm_x4(bl4, wb + 5120u);
                    }
#pragma unroll
                    for (int half = 0; half < 2; ++half) {
                        int g = gp * 2 + half;
                        mma_f16(acc[g], ah, bh4 + half * 2);
                        mma_f16(acc[g], ah, bl4 + half * 2);
                        mma_f16(acc[g], al, bh4 + half * 2);
                    }
                }
            }
            // store W chunk c+1 into the other buffer (safe: after sync_c)
            if (wld) {
                uint4* wd = (uint4*)((char*)smw + 88064 + (cn & 1) * 10240);
                wd[tid] = w0v;
                wd[tid + 256] = w1v;
                if (tid < 128) wd[tid + 512] = w2v;
            }
        }

        // epilogue: all four gates of (row, h-pair) live in this lane's regs
#pragma unroll
        for (int rr = 0; rr < 2; ++rr) {
            int bgr = bi * 64 + wm * 16 + trow + rr * 8;
            float hv[2];
#pragma unroll
            for (int pp = 0; pp < 2; ++pp) {
                int a = rr * 2 + pp;
                float zi = acc[0][a] + br[0][pp];
                float zf = acc[1][a] + br[1][pp];
                float zg = acc[2][a] + br[2][pp];
                float zo = acc[3][a] + br[3][pp];
                float cc = sigf(zf) * cst[a] + sigf(zi) * tanhf(zg);
                cst[a] = cc;
                hv[pp] = sigf(zo) * tanhf(cc);
            }
            __half h0h, h0l, h1h, h1l;
            splith(hv[0], h0h, h0l);
            splith(hv[1], h1h, h1l);
            __half2 ph2; ph2.x = h0h; ph2.y = h1h;
            __half2 pl2; pl2.x = h0l; pl2.y = h1l;
            size_t o = (size_t)bgr * HH + hcol0;
            *(__half2*)&houtH[o] = ph2;
            *(__half2*)&houtL[o] = pl2;
            if (seqH) {
                size_t so = ((size_t)t * BATCH + bgr) * HH + hcol0;
                *(__half2*)&seqH[so] = ph2;
                *(__half2*)&seqL[so] = pl2;
            }
        }
        gbar();   // publish h for next step
    }
    // final h in g_hbh/g_hbl[0]
}

// ---------------------------------------------------------------------------
// Head: reconstruct h = hi+lo; logits -> softmax -> water-filling (R2 logic).
// ---------------------------------------------------------------------------
__device__ __forceinline__ float clip01(float x) {
    return fminf(fmaxf(x, 0.0f), 0.1f);
}
__device__ __forceinline__ float wsum(float v) {
#pragma unroll
    for (int o = 16; o > 0; o >>= 1) v += __shfl_xor_sync(0xffffffffu, v, o);
    return v;
}
__device__ __forceinline__ float wmax(float v) {
#pragma unroll
    for (int o = 16; o > 0; o >>= 1) v = fmaxf(v, __shfl_xor_sync(0xffffffffu, v, o));
    return v;
}

__global__ __launch_bounds__(64) void head_kernel(
    const float* __restrict__ Wout, const float* __restrict__ bout,
    float* __restrict__ out)
{
    __shared__ float hsh[HH];
    __shared__ float lg[OO];
    const int b = blockIdx.x;
    const int tid = threadIdx.x;

    for (int i = tid; i < HH; i += 64)
        hsh[i] = __half2float(g_hbh[0][(size_t)b * HH + i])
               + __half2float(g_hbl[0][(size_t)b * HH + i]);
    __syncthreads();

    if (tid < OO) {
        float a = bout[tid];
        for (int k = 0; k < HH; ++k) a = fmaf(hsh[k], Wout[(size_t)k * OO + tid], a);
        lg[tid] = a;
    }
    __syncthreads();

    if (tid < 32) {
        const bool has1 = (tid + 32) < OO;
        float v0 = lg[tid];
        float v1 = has1 ? lg[tid + 32] : -INFINITY;

        float m  = wmax(fmaxf(v0, v1));
        float e0 = expf(v0 - m);
        float e1 = has1 ? expf(v1 - m) : 0.0f;
        float s  = wsum(e0 + e1);
        float w0 = e0 / s, w1 = e1 / s;

        float old0 = w0, old1 = w1;
        float wc0 = clip01(w0), wc1 = clip01(w1);
        bool done = false;

        for (int it = 0; it < 50; ++it) {
            float leftover = wsum((old0 - wc0) + (old1 - wc1));
            bool m0 = (wc0 != 0.1f), m1 = (wc1 != 0.1f);
            float n0 = m0 ? wc0 : 0.0f;
            float n1 = m1 ? wc1 : 0.0f;
            float denom = wsum(n0 + n1);
            float dd = (denom == 0.0f) ? 1.0f : denom;
            float wn0 = m0 ? wc0 + leftover * n0 / dd : wc0;
            float wn1 = m1 ? wc1 + leftover * n1 / dd : wc1;
            bool over = __any_sync(0xffffffffu, (wn0 > 0.1f) || (wn1 > 0.1f));
            bool ndone = !over;
            float wx0 = ndone ? wn0 : clip01(wn0);
            float wx1 = ndone ? wn1 : clip01(wn1);
            if (!done) { old0 = wn0; old1 = wn1; wc0 = wx0; wc1 = wx1; }
            done = done || ndone;
        }

        out[(size_t)b * OO + tid] = wc0;
        if (has1) out[(size_t)b * OO + tid + 32] = wc1;
    }
}

// ---------------------------------------------------------------------------
// Launch (graph-capturable: kernel launches only)
// ---------------------------------------------------------------------------
extern "C" void kernel_launch(void* const* d_in, const int* in_sizes, int n_in,
                              void* d_out, int out_size)
{
    const float* x    = (const float*)d_in[0];
    const float* W0   = (const float*)d_in[1];
    const float* U0   = (const float*)d_in[2];
    const float* b0   = (const float*)d_in[3];
    const float* W1   = (const float*)d_in[4];
    const float* U1   = (const float*)d_in[5];
    const float* b1   = (const float*)d_in[6];
    const float* Wout = (const float*)d_in[7];
    const float* bout = (const float*)d_in[8];
    float* out = (float*)d_out;

    __half *p_xh = nullptr, *p_xl = nullptr, *p_h0h = nullptr, *p_h0l = nullptr;
    uint4 *p_w0p = nullptr, *p_w1p = nullptr;
    cudaGetSymbolAddress((void**)&p_xh,  g_xh);
    cudaGetSymbolAddress((void**)&p_xl,  g_xl);
    cudaGetSymbolAddress((void**)&p_h0h, g_h0h);
    cudaGetSymbolAddress((void**)&p_h0l, g_h0l);
    cudaGetSymbolAddress((void**)&p_w0p, g_w0p);
    cudaGetSymbolAddress((void**)&p_w1p, g_w1p);

    const int REC_SMEM = 108544;   // U 67584 + A staging 20480 + W staging 20480
    cudaFuncSetAttribute(lstm_fused<128>, cudaFuncAttributeMaxDynamicSharedMemorySize, REC_SMEM);
    cudaFuncSetAttribute(lstm_fused<256>, cudaFuncAttributeMaxDynamicSharedMemorySize, REC_SMEM);

    // Prep: split x and pre-permute/split W0, W1
    split_x_kernel<<<(TT * BATCH * FF / 2) / 256, 256>>>(x);
    split_w_kernel<<<(128 * 1024) / 256, 256>>>(W0, 128, (__half*)p_w0p);
    split_w_kernel<<<(256 * 1024) / 256, 256>>>(W1, 256, (__half*)p_w1p);

    // Layer 0: fused projection + recurrence -> pre-split h0seq planes
    lstm_fused<128><<<256, 256, REC_SMEM>>>(p_xh, p_xl, p_w0p, U0, b0, p_h0h, p_h0l);
    // Layer 1: fused projection + recurrence (final h in g_hbh/g_hbl[0])
    lstm_fused<256><<<256, 256, REC_SMEM>>>(p_h0h, p_h0l, p_w1p, U1, b1, nullptr, nullptr);
    // Head: logits -> softmax -> rebalance
    head_kernel<<<BATCH, 64>>>(Wout, bout, out);
}

// round 13
// speedup vs baseline: 1.2305x; 1.2305x over previous
#include <cuda_runtime.h>
#include <cuda_fp16.h>
#include <math.h>
#include <stdint.h>

// Problem constants
#define BATCH 1024
#define TT    256
#define FF    128
#define HH    256
#define GG    1024   // 4*H
#define OO    50

// ---------------------------------------------------------------------------
// Static device scratch (allocation-free per harness rules)
// ---------------------------------------------------------------------------
__device__ float g_xz[(size_t)TT * BATCH * GG];    // [t][b][g] fp32
__device__ __half g_h0h[(size_t)TT * BATCH * HH];  // layer-0 h seq, hi
__device__ __half g_h0l[(size_t)TT * BATCH * HH];  // layer-0 h seq, lo
__device__ __half g_hbh[2][BATCH * HH];            // h state hi, dbl-buf
__device__ __half g_hbl[2][BATCH * HH];            // h state lo
__device__ unsigned g_gc[16 * 32];                 // per-bi-group counters, 128B apart
__device__ unsigned g_gg[16 * 32];                 // per-bi-group generation words

// ---------------------------------------------------------------------------
// Per-group barrier: only the 16 blocks sharing a batch slice (bi) sync.
// Groups drift independently -> no global straggler coupling.
// ---------------------------------------------------------------------------
__device__ __forceinline__ void gbar_group(int grp) {
    __syncthreads();
    if (threadIdx.x == 0) {
        __threadfence();
        unsigned* cnt = &g_gc[grp * 32];
        unsigned* gw  = &g_gg[grp * 32];
        unsigned gen = *((volatile unsigned*)gw);
        if (atomicAdd(cnt, 1) == 15) {
            atomicExch(cnt, 0);
            __threadfence();
            atomicExch(gw, gen + 1);
        } else {
            while (*((volatile unsigned*)gw) == gen) { __nanosleep(16); }
        }
        __threadfence();
    }
    __syncthreads();
}

__device__ __forceinline__ float sigf(float x) { return 1.0f / (1.0f + expf(-x)); }

// ---------------------------------------------------------------------------
// fp16 mma.sync m16n8k16 (f32 accumulate) + ldmatrix + cp.async helpers
// ---------------------------------------------------------------------------
__device__ __forceinline__ void mma_f16(float* c, const unsigned* a, const unsigned* b) {
    asm volatile(
        "mma.sync.aligned.m16n8k16.row.col.f32.f16.f16.f32 "
        "{%0,%1,%2,%3}, {%4,%5,%6,%7}, {%8,%9}, {%0,%1,%2,%3};"
        : "+f"(c[0]), "+f"(c[1]), "+f"(c[2]), "+f"(c[3])
        : "r"(a[0]), "r"(a[1]), "r"(a[2]), "r"(a[3]), "r"(b[0]), "r"(b[1]));
}
__device__ __forceinline__ void ldsm_x4(unsigned* r, uint32_t addr) {
    asm volatile("ldmatrix.sync.aligned.m8n8.x4.shared.b16 {%0,%1,%2,%3}, [%4];"
        : "=r"(r[0]), "=r"(r[1]), "=r"(r[2]), "=r"(r[3]) : "r"(addr));
}
__device__ __forceinline__ uint32_t smem_u32(const void* p) {
    uint32_t a;
    asm("{ .reg .u64 t; cvta.to.shared.u64 t, %1; cvt.u32.u64 %0, t; }"
        : "=r"(a) : "l"(p));
    return a;
}
__device__ __forceinline__ void cp16(uint32_t dst, const void* src) {
    asm volatile("cp.async.cg.shared.global [%0], [%1], 16;" :: "r"(dst), "l"(src));
}
#define CP_COMMIT() asm volatile("cp.async.commit_group;" ::: "memory")
#define CP_WAIT2()  asm volatile("cp.async.wait_group 2;" ::: "memory")

// split fp32 -> fp16 hi + fp16 lo (hi+lo carries ~22 significand bits)
__device__ __forceinline__ void splith(float f, __half& h, __half& l) {
    h = __float2half_rn(f);
    l = __float2half_rn(f - __half2float(h));
}
__device__ __forceinline__ void split2(float a, float b, unsigned& h, unsigned& l) {
    __half2 h2 = __floats2half2_rn(a, b);
    float ra = a - __low2float(h2);
    float rb = b - __high2float(h2);
    __half2 l2 = __floats2half2_rn(ra, rb);
    h = *(unsigned*)&h2;
    l = *(unsigned*)&l2;
}

// ---------------------------------------------------------------------------
// GEMM + bias (verbatim R8): C[M,1024] = A[M,K] @ W[K,1024] + bias
// fp16 3-term split mma, block 128x64, BK=32, ldmatrix fragments.
// ---------------------------------------------------------------------------
template<bool PERM, bool PRESPLIT>
__global__ __launch_bounds__(256) void gemm_f16(
    const float* __restrict__ A32,
    const __half* __restrict__ Agh, const __half* __restrict__ Agl,
    const float* __restrict__ W, const float* __restrict__ bias,
    float* __restrict__ C, int K)
{
    __shared__ __align__(16) unsigned Ah32[128 * 20];
    __shared__ __align__(16) unsigned Al32[128 * 20];
    __shared__ __align__(16) unsigned Bh32[64 * 20];
    __shared__ __align__(16) unsigned Bl32[64 * 20];
    __half* BhB = (__half*)Bh32;
    __half* BlB = (__half*)Bl32;

    const int tid  = threadIdx.x;
    const int lane = tid & 31;
    const int w    = tid >> 5;
    const int wm   = w & 3, wn = w >> 2;
    const int trow = lane >> 2, q = lane & 3;
    const int m0   = blockIdx.y * 128;
    const int n0   = blockIdx.x * 64;

    const int arow = tid >> 1;
    const int akb  = (tid & 1) * 16;
    const int bk   = tid >> 3;
    const int bnb  = (tid & 7) * 8;

    const uint32_t smA_h = smem_u32(Ah32);
    const uint32_t smA_l = smem_u32(Al32);
    const uint32_t smB_h = smem_u32(Bh32);
    const uint32_t smB_l = smem_u32(Bl32);
    const uint32_t aofs = (uint32_t)(wm * 32 + (lane & 15)) * 80 + ((lane >> 4) & 1) * 16;
    const uint32_t bofs = (uint32_t)(wn * 32 + ((lane >> 4) & 1) * 8 + (lane & 7)) * 80
                        + ((lane >> 3) & 1) * 16;

    float acc[2][4][4];
#pragma unroll
    for (int i = 0; i < 2; ++i)
#pragma unroll
        for (int j = 0; j < 4; ++j)
#pragma unroll
            for (int r = 0; r < 4; ++r) acc[i][j][r] = 0.0f;

    const int iters = K >> 5;

    uint4 pah, pah2, pal, pal2;
    float4 par[4];
    float4 pbr0, pbr1;
    if (PRESPLIT) {
        const __half* ap = Agh + (size_t)(m0 + arow) * K + akb;
        const __half* lp = Agl + (size_t)(m0 + arow) * K + akb;
        pah = *(const uint4*)ap; pah2 = *(const uint4*)(ap + 8);
        pal = *(const uint4*)lp; pal2 = *(const uint4*)(lp + 8);
    } else {
        const float* ap = A32 + (size_t)(m0 + arow) * K + akb;
#pragma unroll
        for (int i = 0; i < 4; ++i) par[i] = *(const float4*)(ap + i * 4);
    }
    pbr0 = *(const float4*)(W + (size_t)bk * GG + n0 + bnb);
    pbr1 = *(const float4*)(W + (size_t)bk * GG + n0 + bnb + 4);

    for (int it = 0; it < iters; ++it) {
        if (PRESPLIT) {
            *(uint4*)&Ah32[arow * 20 + (akb >> 1)]     = pah;
            *(uint4*)&Ah32[arow * 20 + (akb >> 1) + 4] = pah2;
            *(uint4*)&Al32[arow * 20 + (akb >> 1)]     = pal;
            *(uint4*)&Al32[arow * 20 + (akb >> 1) + 4] = pal2;
        } else {
            float f[16];
#pragma unroll
            for (int i = 0; i < 4; ++i) {
                f[i*4+0] = par[i].x; f[i*4+1] = par[i].y;
                f[i*4+2] = par[i].z; f[i*4+3] = par[i].w;
            }
            unsigned h[8], l[8];
#pragma unroll
            for (int j = 0; j < 8; ++j) split2(f[2*j], f[2*j+1], h[j], l[j]);
            *(uint4*)&Ah32[arow * 20 + (akb >> 1)]     = make_uint4(h[0], h[1], h[2], h[3]);
            *(uint4*)&Ah32[arow * 20 + (akb >> 1) + 4] = make_uint4(h[4], h[5], h[6], h[7]);
            *(uint4*)&Al32[arow * 20 + (akb >> 1)]     = make_uint4(l[0], l[1], l[2], l[3]);
            *(uint4*)&Al32[arow * 20 + (akb >> 1) + 4] = make_uint4(l[4], l[5], l[6], l[7]);
        }
        {
            float f[8] = {pbr0.x, pbr0.y, pbr0.z, pbr0.w, pbr1.x, pbr1.y, pbr1.z, pbr1.w};
#pragma unroll
            for (int j = 0; j < 8; ++j) {
                __half hb, lb;
                splith(f[j], hb, lb);
                BhB[(bnb + j) * 40 + bk] = hb;
                BlB[(bnb + j) * 40 + bk] = lb;
            }
        }
        __syncthreads();

        if (it + 1 < iters) {
            int kg = (it + 1) * 32;
            if (PRESPLIT) {
                const __half* ap = Agh + (size_t)(m0 + arow) * K + kg + akb;
                const __half* lp = Agl + (size_t)(m0 + arow) * K + kg + akb;
                pah = *(const uint4*)ap; pah2 = *(const uint4*)(ap + 8);
                pal = *(const uint4*)lp; pal2 = *(const uint4*)(lp + 8);
            } else {
                const float* ap = A32 + (size_t)(m0 + arow) * K + kg + akb;
#pragma unroll
                for (int i = 0; i < 4; ++i) par[i] = *(const float4*)(ap + i * 4);
            }
            pbr0 = *(const float4*)(W + (size_t)(kg + bk) * GG + n0 + bnb);
            pbr1 = *(const float4*)(W + (size_t)(kg + bk) * GG + n0 + bnb + 4);
        }

#pragma unroll
        for (int s = 0; s < 2; ++s) {
            unsigned ah[2][4], al[2][4], bh[2][4], bl[2][4];
#pragma unroll
            for (int mt = 0; mt < 2; ++mt) {
                ldsm_x4(ah[mt], smA_h + aofs + mt * 1280 + s * 32);
                ldsm_x4(al[mt], smA_l + aofs + mt * 1280 + s * 32);
            }
#pragma unroll
            for (int np = 0; np < 2; ++np) {
                ldsm_x4(bh[np], smB_h + bofs + np * 1280 + s * 32);
                ldsm_x4(bl[np], smB_l + bofs + np * 1280 + s * 32);
            }
#pragma unroll
            for (int np = 0; np < 2; ++np)
#pragma unroll
                for (int half = 0; half < 2; ++half) {
                    int nt = np * 2 + half;
#pragma unroll
                    for (int mt = 0; mt < 2; ++mt) {
                        mma_f16(acc[mt][nt], ah[mt], bh[np] + half * 2);
                        mma_f16(acc[mt][nt], ah[mt], bl[np] + half * 2);
                        mma_f16(acc[mt][nt], al[mt], bh[np] + half * 2);
                    }
                }
        }
        __syncthreads();
    }

#pragma unroll
    for (int mt = 0; mt < 2; ++mt) {
        int row0 = m0 + wm * 32 + mt * 16 + trow;
#pragma unroll
        for (int nt = 0; nt < 4; ++nt) {
            int col = n0 + wn * 32 + nt * 8 + 2 * q;
            float b0 = bias[col], b1 = bias[col + 1];
#pragma unroll
            for (int hr = 0; hr < 2; ++hr) {
                size_t mm = (size_t)(row0 + hr * 8);
                size_t orow = PERM ? ((mm & (TT - 1)) * (size_t)BATCH + (mm >> 8)) : mm;
                float2 o;
                o.x = acc[mt][nt][hr * 2 + 0] + b0;
                o.y = acc[mt][nt][hr * 2 + 1] + b1;
                *(float2*)(C + orow * (size_t)GG + col) = o;
            }
        }
    }
}

// ---------------------------------------------------------------------------
// Persistent LSTM layer, fp16 split mma. Changes vs R8:
//  * h staging via cp.async.cg into a 4-deep ring (3 groups in flight,
//    wait_group(2), always-commit) -> 1 syncthreads/chunk, no prefetch regs.
//  * per-bi 16-block group barrier instead of 256-block grid barrier.
// SMEM (bytes): Uh 0, Ul 33792, ring buf b at 67584+b*10240 (hi) /+5120 (lo).
// ---------------------------------------------------------------------------
__global__ __launch_bounds__(256, 2) void lstm_rec_tc(
    const float* __restrict__ xz,      // [T][B][G] fp32
    const float* __restrict__ U,       // [H][G] fp32
    __half* __restrict__ seqH,         // [T][B][H] or null
    __half* __restrict__ seqL)
{
    extern __shared__ __align__(16) unsigned smw[];
    __half* UhE = (__half*)smw;
    __half* UlE = (__half*)(smw + 8448);

    const int tid  = threadIdx.x;
    const int lane = tid & 31;
    const int w    = tid >> 5;
    const int wm   = w & 3, wn = w >> 2;
    const int trow = lane >> 2, q = lane & 3;
    const int bi   = blockIdx.x >> 4;
    const int hj   = blockIdx.x & 15;

    // ---- load + split U slice (resident, gate-permuted)
    for (int idx = tid; idx < 64 * 256; idx += 256) {
        int n = idx & 63, k = idx >> 6;
        int gcol = ((n >> 3) & 3) * HH + hj * 16 + (n >> 5) * 8 + (n & 7);
        float v = U[(size_t)k * GG + gcol];
        __half hb, lb;
        splith(v, hb, lb);
        UhE[n * 264 + k] = hb;
        UlE[n * 264 + k] = lb;
    }
    // ---- zero h-state buffer 0 (this block's cols)
    {
        int r = tid >> 2, c0 = (tid & 3) * 4;
        uint2 z = make_uint2(0u, 0u);
        *(uint2*)&g_hbh[0][(size_t)(bi * 64 + r) * HH + hj * 16 + c0] = z;
        *(uint2*)&g_hbl[0][(size_t)(bi * 64 + r) * HH + hj * 16 + c0] = z;
    }
    gbar_group(bi);

    const uint32_t usm = smem_u32(smw);
    // 4-slot staging ring: hi at 67584 + b*10240, lo at +5120
    const uint32_t aofs = (uint32_t)(wm * 16 + (lane & 15)) * 80 + ((lane >> 4) & 1) * 16;
    const uint32_t bofsU = (uint32_t)(wn * 32 + ((lane >> 4) & 1) * 8 + (lane & 7)) * 528
                         + ((lane >> 3) & 1) * 16;

    const int hcol0 = hj * 16 + wn * 8 + 2 * q;
    const int frow  = tid >> 2;           // fill row 0..63
    const int fseg  = tid & 3;            // fill 16B segment 0..3
    const uint32_t fdst = frow * 80 + fseg * 16;    // within-plane byte offset
    const int fsrc  = fseg * 8;           // halves offset within chunk

    float cst[4] = {0.f, 0.f, 0.f, 0.f};

    for (int t = 0; t < TT; ++t) {
        const __half* hinH = g_hbh[t & 1];
        const __half* hinL = g_hbl[t & 1];
        __half* houtH = g_hbh[(t + 1) & 1];
        __half* houtL = g_hbl[(t + 1) & 1];

        const __half* hrowH = hinH + (size_t)(bi * 64 + frow) * HH + fsrc;
        const __half* hrowL = hinL + (size_t)(bi * 64 + frow) * HH + fsrc;

        // xz prefetch (consumed in epilogue)
        float2 xv[2][4];
#pragma unroll
        for (int rr = 0; rr < 2; ++rr) {
            int bgr = bi * 64 + wm * 16 + trow + rr * 8;
            const float* xp = xz + ((size_t)t * BATCH + bgr) * GG + hcol0;
#pragma unroll
            for (int g = 0; g < 4; ++g) xv[rr][g] = *(const float2*)(xp + g * 256);
        }

        // ---- prologue: issue chunks 0..2 into ring slots 0..2
#pragma unroll
        for (int c = 0; c < 3; ++c) {
            uint32_t base = usm + 67584u + (uint32_t)c * 10240u + fdst;
            cp16(base,          hrowH + c * 32);
            cp16(base + 5120u,  hrowL + c * 32);
            CP_COMMIT();
        }

        float acc[4][4];
#pragma unroll
        for (int g = 0; g < 4; ++g)
#pragma unroll
            for (int r = 0; r < 4; ++r) acc[g][r] = 0.0f;

        for (int c = 0; c < 8; ++c) {
            const int cb = c & 3;
            CP_WAIT2();          // groups <= c complete (always-commit keeps count uniform)
            __syncthreads();     // chunk c visible to all; all warps done chunk c-1

#pragma unroll
            for (int s = 0; s < 2; ++s) {
                unsigned ah[4], al[4];
                uint32_t ab = usm + 67584u + (uint32_t)cb * 10240u + aofs + s * 32;
                ldsm_x4(ah, ab);
                ldsm_x4(al, ab + 5120u);
#pragma unroll
                for (int gp = 0; gp < 2; ++gp) {
                    unsigned bh4[4], bl4[4];
                    uint32_t ub = usm + bofsU + gp * 8448 + c * 64 + s * 32;
                    ldsm_x4(bh4, ub);
                    ldsm_x4(bl4, ub + 33792u);
#pragma unroll
                    for (int half = 0; half < 2; ++half) {
                        int g = gp * 2 + half;
                        mma_f16(acc[g], ah, bh4 + half * 2);
                        mma_f16(acc[g], ah, bl4 + half * 2);
                        mma_f16(acc[g], al, bh4 + half * 2);
                    }
                }
            }
            // issue chunk c+3 into slot (c+3)&3 == (c-1)&3 (all warps done c-1)
            if (c + 3 < 8) {
                uint32_t base = usm + 67584u + (uint32_t)((c + 3) & 3) * 10240u + fdst;
                cp16(base,         hrowH + (c + 3) * 32);
                cp16(base + 5120u, hrowL + (c + 3) * 32);
            }
            CP_COMMIT();   // unconditional: keeps pending-group count uniform
        }

        // epilogue: all four gates of (row, h-pair) live in this lane's regs
#pragma unroll
        for (int rr = 0; rr < 2; ++rr) {
            int bgr = bi * 64 + wm * 16 + trow + rr * 8;
            float hv[2];
#pragma unroll
            for (int pp = 0; pp < 2; ++pp) {
                int a = rr * 2 + pp;
                float zi = acc[0][a] + (pp ? xv[rr][0].y : xv[rr][0].x);
                float zf = acc[1][a] + (pp ? xv[rr][1].y : xv[rr][1].x);
                float zg = acc[2][a] + (pp ? xv[rr][2].y : xv[rr][2].x);
                float zo = acc[3][a] + (pp ? xv[rr][3].y : xv[rr][3].x);
                float cc = sigf(zf) * cst[a] + sigf(zi) * tanhf(zg);
                cst[a] = cc;
                hv[pp] = sigf(zo) * tanhf(cc);
            }
            __half h0h, h0l, h1h, h1l;
            splith(hv[0], h0h, h0l);
            splith(hv[1], h1h, h1l);
            __half2 ph2; ph2.x = h0h; ph2.y = h1h;
            __half2 pl2; pl2.x = h0l; pl2.y = h1l;
            size_t o = (size_t)bgr * HH + hcol0;
            *(__half2*)&houtH[o] = ph2;
            *(__half2*)&houtL[o] = pl2;
            if (seqH) {
                size_t so = ((size_t)t * BATCH + bgr) * HH + hcol0;
                *(__half2*)&seqH[so] = ph2;
                *(__half2*)&seqL[so] = pl2;
            }
        }
        gbar_group(bi);   // publish h to the 16 blocks of this batch slice
    }
    // final h in g_hbh/g_hbl[0]
}

// ---------------------------------------------------------------------------
// Head: reconstruct h = hi+lo; logits -> softmax -> water-filling (R2 logic).
// ---------------------------------------------------------------------------
__device__ __forceinline__ float clip01(float x) {
    return fminf(fmaxf(x, 0.0f), 0.1f);
}
__device__ __forceinline__ float wsum(float v) {
#pragma unroll
    for (int o = 16; o > 0; o >>= 1) v += __shfl_xor_sync(0xffffffffu, v, o);
    return v;
}
__device__ __forceinline__ float wmax(float v) {
#pragma unroll
    for (int o = 16; o > 0; o >>= 1) v = fmaxf(v, __shfl_xor_sync(0xffffffffu, v, o));
    return v;
}

__global__ __launch_bounds__(64) void head_kernel(
    const float* __restrict__ Wout, const float* __restrict__ bout,
    float* __restrict__ out)
{
    __shared__ float hsh[HH];
    __shared__ float lg[OO];
    const int b = blockIdx.x;
    const int tid = threadIdx.x;

    for (int i = tid; i < HH; i += 64)
        hsh[i] = __half2float(g_hbh[0][(size_t)b * HH + i])
               + __half2float(g_hbl[0][(size_t)b * HH + i]);
    __syncthreads();

    if (tid < OO) {
        float a = bout[tid];
        for (int k = 0; k < HH; ++k) a = fmaf(hsh[k], Wout[(size_t)k * OO + tid], a);
        lg[tid] = a;
    }
    __syncthreads();

    if (tid < 32) {
        const bool has1 = (tid + 32) < OO;
        float v0 = lg[tid];
        float v1 = has1 ? lg[tid + 32] : -INFINITY;

        float m  = wmax(fmaxf(v0, v1));
        float e0 = expf(v0 - m);
        float e1 = has1 ? expf(v1 - m) : 0.0f;
        float s  = wsum(e0 + e1);
        float w0 = e0 / s, w1 = e1 / s;

        float old0 = w0, old1 = w1;
        float wc0 = clip01(w0), wc1 = clip01(w1);
        bool done = false;

        for (int it = 0; it < 50; ++it) {
            float leftover = wsum((old0 - wc0) + (old1 - wc1));
            bool m0 = (wc0 != 0.1f), m1 = (wc1 != 0.1f);
            float n0 = m0 ? wc0 : 0.0f;
            float n1 = m1 ? wc1 : 0.0f;
            float denom = wsum(n0 + n1);
            float dd = (denom == 0.0f) ? 1.0f : denom;
            float wn0 = m0 ? wc0 + leftover * n0 / dd : wc0;
            float wn1 = m1 ? wc1 + leftover * n1 / dd : wc1;
            bool over = __any_sync(0xffffffffu, (wn0 > 0.1f) || (wn1 > 0.1f));
            bool ndone = !over;
            float wx0 = ndone ? wn0 : clip01(wn0);
            float wx1 = ndone ? wn1 : clip01(wn1);
            if (!done) { old0 = wn0; old1 = wn1; wc0 = wx0; wc1 = wx1; }
            done = done || ndone;
        }

        out[(size_t)b * OO + tid] = wc0;
        if (has1) out[(size_t)b * OO + tid + 32] = wc1;
    }
}

// ---------------------------------------------------------------------------
// Launch (graph-capturable: kernel launches only)
// ---------------------------------------------------------------------------
extern "C" void kernel_launch(void* const* d_in, const int* in_sizes, int n_in,
                              void* d_out, int out_size)
{
    const float* x    = (const float*)d_in[0];
    const float* W0   = (const float*)d_in[1];
    const float* U0   = (const float*)d_in[2];
    const float* b0   = (const float*)d_in[3];
    const float* W1   = (const float*)d_in[4];
    const float* U1   = (const float*)d_in[5];
    const float* b1   = (const float*)d_in[6];
    const float* Wout = (const float*)d_in[7];
    const float* bout = (const float*)d_in[8];
    float* out = (float*)d_out;

    float* p_xz = nullptr;
    __half *p_h0h = nullptr, *p_h0l = nullptr;
    cudaGetSymbolAddress((void**)&p_xz,  g_xz);
    cudaGetSymbolAddress((void**)&p_h0h, g_h0h);
    cudaGetSymbolAddress((void**)&p_h0l, g_h0l);

    const int REC_SMEM = 108544;   // U hi/lo (67584) + 4-slot cp.async ring (40960)
    cudaFuncSetAttribute(lstm_rec_tc, cudaFuncAttributeMaxDynamicSharedMemorySize, REC_SMEM);

    dim3 gg(GG / 64, (BATCH * TT) / 128);   // (16, 2048)

    // Layer 0 input projection: xz0[t][b][g]
    gemm_f16<true, false><<<gg, 256>>>(x, nullptr, nullptr, W0, b0, p_xz, FF);
    // Layer 0 recurrence -> pre-split h0seq planes
    lstm_rec_tc<<<256, 256, REC_SMEM>>>(p_xz, U0, p_h0h, p_h0l);
    // Layer 1 input projection (A pre-split, reuses g_xz)
    gemm_f16<false, true><<<gg, 256>>>(nullptr, p_h0h, p_h0l, W1, b1, p_xz, HH);
    // Layer 1 recurrence (final h ends in g_hbh/g_hbl[0])
    lstm_rec_tc<<<256, 256, REC_SMEM>>>(p_xz, U1, nullptr, nullptr);
    // Head: logits -> softmax -> rebalance
    head_kernel<<<BATCH, 64>>>(Wout, bout, out);
}

// round 15
// speedup vs baseline: 1.5139x; 1.2303x over previous
#include <cuda_runtime.h>
#include <cuda_fp16.h>
#include <math.h>
#include <stdint.h>

// Problem constants
#define BATCH 1024
#define TT    256
#define FF    128
#define HH    256
#define GG    1024   // 4*H
#define OO    50

// ---------------------------------------------------------------------------
// Static device scratch (allocation-free per harness rules)
// ---------------------------------------------------------------------------
__device__ float g_xz[(size_t)TT * BATCH * GG];    // [t][b][g] fp32
__device__ __align__(16) __half g_axh[(size_t)BATCH * TT * FF];  // x split hi ([b*T+t][f])
__device__ __align__(16) __half g_axl[(size_t)BATCH * TT * FF];  // x split lo
__device__ __align__(16) __half g_w0th[1024 * 128];  // W0^T hi  [n][k]
__device__ __align__(16) __half g_w0tl[1024 * 128];  // W0^T lo
__device__ __align__(16) __half g_w1th[1024 * 256];  // W1^T hi
__device__ __align__(16) __half g_w1tl[1024 * 256];  // W1^T lo
__device__ __half g_h0h[(size_t)TT * BATCH * HH];  // layer-0 h seq, hi
__device__ __half g_h0l[(size_t)TT * BATCH * HH];  // layer-0 h seq, lo
__device__ __half g_hbh[2][BATCH * HH];            // h state hi, dbl-buf
__device__ __half g_hbl[2][BATCH * HH];            // h state lo
__device__ unsigned g_gc[16 * 32];                 // per-bi-group counters, 128B apart
__device__ unsigned g_gg[16 * 32];                 // per-bi-group generation words

// ---------------------------------------------------------------------------
// Per-group barrier (proven R12): 16 blocks sharing a batch slice sync.
// ---------------------------------------------------------------------------
__device__ __forceinline__ void gbar_group(int grp) {
    __syncthreads();
    if (threadIdx.x == 0) {
        __threadfence();
        unsigned* cnt = &g_gc[grp * 32];
        unsigned* gw  = &g_gg[grp * 32];
        unsigned gen = *((volatile unsigned*)gw);
        if (atomicAdd(cnt, 1) == 15) {
            atomicExch(cnt, 0);
            __threadfence();
            atomicExch(gw, gen + 1);
        } else {
            while (*((volatile unsigned*)gw) == gen) { __nanosleep(16); }
        }
        __threadfence();
    }
    __syncthreads();
}

__device__ __forceinline__ float sigf(float x) { return 1.0f / (1.0f + expf(-x)); }

// ---------------------------------------------------------------------------
// fp16 mma.sync m16n8k16 (f32 accumulate) + ldmatrix + cp.async helpers
// ---------------------------------------------------------------------------
__device__ __forceinline__ void mma_f16(float* c, const unsigned* a, const unsigned* b) {
    asm volatile(
        "mma.sync.aligned.m16n8k16.row.col.f32.f16.f16.f32 "
        "{%0,%1,%2,%3}, {%4,%5,%6,%7}, {%8,%9}, {%0,%1,%2,%3};"
        : "+f"(c[0]), "+f"(c[1]), "+f"(c[2]), "+f"(c[3])
        : "r"(a[0]), "r"(a[1]), "r"(a[2]), "r"(a[3]), "r"(b[0]), "r"(b[1]));
}
__device__ __forceinline__ void ldsm_x4(unsigned* r, uint32_t addr) {
    asm volatile("ldmatrix.sync.aligned.m8n8.x4.shared.b16 {%0,%1,%2,%3}, [%4];"
        : "=r"(r[0]), "=r"(r[1]), "=r"(r[2]), "=r"(r[3]) : "r"(addr));
}
__device__ __forceinline__ uint32_t smem_u32(const void* p) {
    uint32_t a;
    asm("{ .reg .u64 t; cvta.to.shared.u64 t, %1; cvt.u32.u64 %0, t; }"
        : "=r"(a) : "l"(p));
    return a;
}
__device__ __forceinline__ void cp16(uint32_t dst, const void* src) {
    asm volatile("cp.async.cg.shared.global [%0], [%1], 16;" :: "r"(dst), "l"(src));
}
#define CP_COMMIT() asm volatile("cp.async.commit_group;" ::: "memory")
#define CP_WAIT1()  asm volatile("cp.async.wait_group 1;" ::: "memory")
#define CP_WAIT2()  asm volatile("cp.async.wait_group 2;" ::: "memory")

// split fp32 -> fp16 hi + fp16 lo (hi+lo carries ~22 significand bits)
__device__ __forceinline__ void splith(float f, __half& h, __half& l) {
    h = __float2half_rn(f);
    l = __float2half_rn(f - __half2float(h));
}
__device__ __forceinline__ void split2(float a, float b, unsigned& h, unsigned& l) {
    __half2 h2 = __floats2half2_rn(a, b);
    float ra = a - __low2float(h2);
    float rb = b - __high2float(h2);
    __half2 l2 = __floats2half2_rn(ra, rb);
    h = *(unsigned*)&h2;
    l = *(unsigned*)&l2;
}

// ---------------------------------------------------------------------------
// Prep: split x (identity layout [b*T+t][f]) -> fp16 hi/lo planes
// ---------------------------------------------------------------------------
__global__ __launch_bounds__(256) void split_x_kernel(const float* __restrict__ x) {
    size_t i = ((size_t)blockIdx.x * 256 + threadIdx.x) * 2;
    float2 v = *(const float2*)(x + i);
    unsigned h, l;
    split2(v.x, v.y, h, l);
    *(unsigned*)(g_axh + i) = h;
    *(unsigned*)(g_axl + i) = l;
}

// ---------------------------------------------------------------------------
// Prep: transpose + split W [K][1024] -> Wt planes [1024][K]
// ---------------------------------------------------------------------------
__global__ __launch_bounds__(256) void split_wt_kernel(
    const float* __restrict__ W, int K,
    __half* __restrict__ th, __half* __restrict__ tl) {
    int idx = blockIdx.x * 256 + threadIdx.x;     // over 1024*K
    if (idx >= 1024 * K) return;
    int k = idx % K, n = idx / K;
    __half hb, lb;
    splith(W[(size_t)k * GG + n], hb, lb);
    th[(size_t)n * K + k] = hb;
    tl[(size_t)n * K + k] = lb;
}

// ---------------------------------------------------------------------------
// GEMM + bias, cp.async 3-slot pipeline: C[M,1024] = A[M,K] @ W[K,1024] + bias
// A: presplit fp16 planes [M][K].  B: pre-transposed+split planes [1024][K].
// Block 128x64, BK=32, 256 thr = 8 warps (4M x 2N); 1 syncthreads/iter.
// Stage (30720 B): Ah +0 (128x80B), Al +10240, Bh +20480 (64x80B), Bl +25600.
// PERM: output rows m=b*T+t -> t*B+b (layer-0 xz layout).
// ---------------------------------------------------------------------------
#define GSTG 30720
template<bool PERM>
__global__ __launch_bounds__(256, 2) void gemm_f16(
    const __half* __restrict__ Agh, const __half* __restrict__ Agl,
    const __half* __restrict__ Bth, const __half* __restrict__ Btl,
    const float* __restrict__ bias, float* __restrict__ C, int K)
{
    extern __shared__ __align__(16) char gsm[];
    const uint32_t sb = smem_u32(gsm);

    const int tid  = threadIdx.x;
    const int lane = tid & 31;
    const int w    = tid >> 5;
    const int wm   = w & 3, wn = w >> 2;
    const int trow = lane >> 2, q = lane & 3;
    const int m0   = blockIdx.y * 128;
    const int n0   = blockIdx.x * 64;

    // cp.async fill assignments
    const int arw = tid >> 1;                 // A row 0..127
    const int ac  = (tid & 1) * 16;           // A k-offset (halves)
    const int brw = tid >> 2;                 // B n-row 0..63
    const int bc  = (tid & 3) * 8;            // B k-offset (halves)
    const uint32_t adst = (uint32_t)arw * 80 + (uint32_t)(tid & 1) * 32;
    const uint32_t bdst = 20480u + (uint32_t)brw * 80 + (uint32_t)(tid & 3) * 16;

    const __half* aH = Agh + (size_t)(m0 + arw) * K + ac;
    const __half* aL = Agl + (size_t)(m0 + arw) * K + ac;
    const __half* bH = Bth + (size_t)(n0 + brw) * K + bc;
    const __half* bL = Btl + (size_t)(n0 + brw) * K + bc;

    // fragment bases (geometry identical to R8/R12)
    const uint32_t aofs = (uint32_t)(wm * 32 + (lane & 15)) * 80 + ((lane >> 4) & 1) * 16;
    const uint32_t bofs = 20480u
        + (uint32_t)(wn * 32 + ((lane >> 4) & 1) * 8 + (lane & 7)) * 80
        + ((lane >> 3) & 1) * 16;

    float acc[2][4][4];
#pragma unroll
    for (int i = 0; i < 2; ++i)
#pragma unroll
        for (int j = 0; j < 4; ++j)
#pragma unroll
            for (int r = 0; r < 4; ++r) acc[i][j][r] = 0.0f;

    const int iters = K >> 5;

    // prologue: issue chunks 0,1 into slots 0,1
#pragma unroll
    for (int c = 0; c < 2; ++c) {
        uint32_t s = sb + (uint32_t)c * GSTG;
        cp16(s + adst,           aH + c * 32);
        cp16(s + adst + 16,      aH + c * 32 + 8);
        cp16(s + 10240 + adst,      aL + c * 32);
        cp16(s + 10240 + adst + 16, aL + c * 32 + 8);
        cp16(s + bdst,          bH + c * 32);
        cp16(s + 5120 + bdst,   bL + c * 32);
        CP_COMMIT();
    }

    for (int c = 0; c < iters; ++c) {
        const uint32_t slot = sb + (uint32_t)(c % 3) * GSTG;
        CP_WAIT1();          // chunk c resident (pending <= 1)
        __syncthreads();     // visible block-wide; all warps done chunk c-1

#pragma unroll
        for (int s = 0; s < 2; ++s) {
            unsigned ah[2][4], al[2][4], bh[2][4], bl[2][4];
#pragma unroll
            for (int mt = 0; mt < 2; ++mt) {
                ldsm_x4(ah[mt], slot + aofs + mt * 1280 + s * 32);
                ldsm_x4(al[mt], slot + 10240u + aofs + mt * 1280 + s * 32);
            }
#pragma unroll
            for (int np = 0; np < 2; ++np) {
                ldsm_x4(bh[np], slot + bofs + np * 1280 + s * 32);
                ldsm_x4(bl[np], slot + 5120u + bofs + np * 1280 + s * 32);
            }
#pragma unroll
            for (int np = 0; np < 2; ++np)
#pragma unroll
                for (int half = 0; half < 2; ++half) {
                    int nt = np * 2 + half;
#pragma unroll
                    for (int mt = 0; mt < 2; ++mt) {
                        mma_f16(acc[mt][nt], ah[mt], bh[np] + half * 2);
                        mma_f16(acc[mt][nt], ah[mt], bl[np] + half * 2);
                        mma_f16(acc[mt][nt], al[mt], bh[np] + half * 2);
                    }
                }
        }
        // issue chunk c+2 into slot (c+2)%3 (safe: after this iter's sync)
        if (c + 2 < iters) {
            uint32_t s2 = sb + (uint32_t)((c + 2) % 3) * GSTG;
            cp16(s2 + adst,           aH + (c + 2) * 32);
            cp16(s2 + adst + 16,      aH + (c + 2) * 32 + 8);
            cp16(s2 + 10240 + adst,      aL + (c + 2) * 32);
            cp16(s2 + 10240 + adst + 16, aL + (c + 2) * 32 + 8);
            cp16(s2 + bdst,          bH + (c + 2) * 32);
            cp16(s2 + 5120 + bdst,   bL + (c + 2) * 32);
        }
        CP_COMMIT();   // unconditional: uniform group accounting
    }

    // epilogue (identical to R8/R12)
#pragma unroll
    for (int mt = 0; mt < 2; ++mt) {
        int row0 = m0 + wm * 32 + mt * 16 + trow;
#pragma unroll
        for (int nt = 0; nt < 4; ++nt) {
            int col = n0 + wn * 32 + nt * 8 + 2 * q;
            float b0 = bias[col], b1 = bias[col + 1];
#pragma unroll
            for (int hr = 0; hr < 2; ++hr) {
                size_t mm = (size_t)(row0 + hr * 8);
                size_t orow = PERM ? ((mm & (TT - 1)) * (size_t)BATCH + (mm >> 8)) : mm;
                float2 o;
                o.x = acc[mt][nt][hr * 2 + 0] + b0;
                o.y = acc[mt][nt][hr * 2 + 1] + b1;
                *(float2*)(C + orow * (size_t)GG + col) = o;
            }
        }
    }
}

// ---------------------------------------------------------------------------
// Persistent LSTM layer (byte-identical to R12 champion).
// ---------------------------------------------------------------------------
__global__ __launch_bounds__(256, 2) void lstm_rec_tc(
    const float* __restrict__ xz,      // [T][B][G] fp32
    const float* __restrict__ U,       // [H][G] fp32
    __half* __restrict__ seqH,         // [T][B][H] or null
    __half* __restrict__ seqL)
{
    extern __shared__ __align__(16) unsigned smw[];
    __half* UhE = (__half*)smw;
    __half* UlE = (__half*)(smw + 8448);

    const int tid  = threadIdx.x;
    const int lane = tid & 31;
    const int w    = tid >> 5;
    const int wm   = w & 3, wn = w >> 2;
    const int trow = lane >> 2, q = lane & 3;
    const int bi   = blockIdx.x >> 4;
    const int hj   = blockIdx.x & 15;

    for (int idx = tid; idx < 64 * 256; idx += 256) {
        int n = idx & 63, k = idx >> 6;
        int gcol = ((n >> 3) & 3) * HH + hj * 16 + (n >> 5) * 8 + (n & 7);
        float v = U[(size_t)k * GG + gcol];
        __half hb, lb;
        splith(v, hb, lb);
        UhE[n * 264 + k] = hb;
        UlE[n * 264 + k] = lb;
    }
    {
        int r = tid >> 2, c0 = (tid & 3) * 4;
        uint2 z = make_uint2(0u, 0u);
        *(uint2*)&g_hbh[0][(size_t)(bi * 64 + r) * HH + hj * 16 + c0] = z;
        *(uint2*)&g_hbl[0][(size_t)(bi * 64 + r) * HH + hj * 16 + c0] = z;
    }
    gbar_group(bi);

    const uint32_t usm = smem_u32(smw);
    const uint32_t aofs = (uint32_t)(wm * 16 + (lane & 15)) * 80 + ((lane >> 4) & 1) * 16;
    const uint32_t bofsU = (uint32_t)(wn * 32 + ((lane >> 4) & 1) * 8 + (lane & 7)) * 528
                         + ((lane >> 3) & 1) * 16;

    const int hcol0 = hj * 16 + wn * 8 + 2 * q;
    const int frow  = tid >> 2;
    const int fseg  = tid & 3;
    const uint32_t fdst = frow * 80 + fseg * 16;
    const int fsrc  = fseg * 8;

    float cst[4] = {0.f, 0.f, 0.f, 0.f};

    for (int t = 0; t < TT; ++t) {
        const __half* hinH = g_hbh[t & 1];
        const __half* hinL = g_hbl[t & 1];
        __half* houtH = g_hbh[(t + 1) & 1];
        __half* houtL = g_hbl[(t + 1) & 1];

        const __half* hrowH = hinH + (size_t)(bi * 64 + frow) * HH + fsrc;
        const __half* hrowL = hinL + (size_t)(bi * 64 + frow) * HH + fsrc;

        float2 xv[2][4];
#pragma unroll
        for (int rr = 0; rr < 2; ++rr) {
            int bgr = bi * 64 + wm * 16 + trow + rr * 8;
            const float* xp = xz + ((size_t)t * BATCH + bgr) * GG + hcol0;
#pragma unroll
            for (int g = 0; g < 4; ++g) xv[rr][g] = *(const float2*)(xp + g * 256);
        }

#pragma unroll
        for (int c = 0; c < 3; ++c) {
            uint32_t base = usm + 67584u + (uint32_t)c * 10240u + fdst;
            cp16(base,          hrowH + c * 32);
            cp16(base + 5120u,  hrowL + c * 32);
            CP_COMMIT();
        }

        float acc[4][4];
#pragma unroll
        for (int g = 0; g < 4; ++g)
#pragma unroll
            for (int r = 0; r < 4; ++r) acc[g][r] = 0.0f;

        for (int c = 0; c < 8; ++c) {
            const int cb = c & 3;
            CP_WAIT2();
            __syncthreads();

#pragma unroll
            for (int s = 0; s < 2; ++s) {
                unsigned ah[4], al[4];
                uint32_t ab = usm + 67584u + (uint32_t)cb * 10240u + aofs + s * 32;
                ldsm_x4(ah, ab);
                ldsm_x4(al, ab + 5120u);
#pragma unroll
                for (int gp = 0; gp < 2; ++gp) {
                    unsigned bh4[4], bl4[4];
                    uint32_t ub = usm + bofsU + gp * 8448 + c * 64 + s * 32;
                    ldsm_x4(bh4, ub);
                    ldsm_x4(bl4, ub + 33792u);
#pragma unroll
                    for (int half = 0; half < 2; ++half) {
                        int g = gp * 2 + half;
                        mma_f16(acc[g], ah, bh4 + half * 2);
                        mma_f16(acc[g], ah, bl4 + half * 2);
                        mma_f16(acc[g], al, bh4 + half * 2);
                    }
                }
            }
            if (c + 3 < 8) {
                uint32_t base = usm + 67584u + (uint32_t)((c + 3) & 3) * 10240u + fdst;
                cp16(base,         hrowH + (c + 3) * 32);
                cp16(base + 5120u, hrowL + (c + 3) * 32);
            }
            CP_COMMIT();
        }

#pragma unroll
        for (int rr = 0; rr < 2; ++rr) {
            int bgr = bi * 64 + wm * 16 + trow + rr * 8;
            float hv[2];
#pragma unroll
            for (int pp = 0; pp < 2; ++pp) {
                int a = rr * 2 + pp;
                float zi = acc[0][a] + (pp ? xv[rr][0].y : xv[rr][0].x);
                float zf = acc[1][a] + (pp ? xv[rr][1].y : xv[rr][1].x);
                float zg = acc[2][a] + (pp ? xv[rr][2].y : xv[rr][2].x);
                float zo = acc[3][a] + (pp ? xv[rr][3].y : xv[rr][3].x);
                float cc = sigf(zf) * cst[a] + sigf(zi) * tanhf(zg);
                cst[a] = cc;
                hv[pp] = sigf(zo) * tanhf(cc);
            }
            __half h0h, h0l, h1h, h1l;
            splith(hv[0], h0h, h0l);
            splith(hv[1], h1h, h1l);
            __half2 ph2; ph2.x = h0h; ph2.y = h1h;
            __half2 pl2; pl2.x = h0l; pl2.y = h1l;
            size_t o = (size_t)bgr * HH + hcol0;
            *(__half2*)&houtH[o] = ph2;
            *(__half2*)&houtL[o] = pl2;
            if (seqH) {
                size_t so = ((size_t)t * BATCH + bgr) * HH + hcol0;
                *(__half2*)&seqH[so] = ph2;
                *(__half2*)&seqL[so] = pl2;
            }
        }
        gbar_group(bi);
    }
}

// ---------------------------------------------------------------------------
// Head (byte-identical to R12)
// ---------------------------------------------------------------------------
__device__ __forceinline__ float clip01(float x) {
    return fminf(fmaxf(x, 0.0f), 0.1f);
}
__device__ __forceinline__ float wsum(float v) {
#pragma unroll
    for (int o = 16; o > 0; o >>= 1) v += __shfl_xor_sync(0xffffffffu, v, o);
    return v;
}
__device__ __forceinline__ float wmax(float v) {
#pragma unroll
    for (int o = 16; o > 0; o >>= 1) v = fmaxf(v, __shfl_xor_sync(0xffffffffu, v, o));
    return v;
}

__global__ __launch_bounds__(64) void head_kernel(
    const float* __restrict__ Wout, const float* __restrict__ bout,
    float* __restrict__ out)
{
    __shared__ float hsh[HH];
    __shared__ float lg[OO];
    const int b = blockIdx.x;
    const int tid = threadIdx.x;

    for (int i = tid; i < HH; i += 64)
        hsh[i] = __half2float(g_hbh[0][(size_t)b * HH + i])
               + __half2float(g_hbl[0][(size_t)b * HH + i]);
    __syncthreads();

    if (tid < OO) {
        float a = bout[tid];
        for (int k = 0; k < HH; ++k) a = fmaf(hsh[k], Wout[(size_t)k * OO + tid], a);
        lg[tid] = a;
    }
    __syncthreads();

    if (tid < 32) {
        const bool has1 = (tid + 32) < OO;
        float v0 = lg[tid];
        float v1 = has1 ? lg[tid + 32] : -INFINITY;

        float m  = wmax(fmaxf(v0, v1));
        float e0 = expf(v0 - m);
        float e1 = has1 ? expf(v1 - m) : 0.0f;
        float s  = wsum(e0 + e1);
        float w0 = e0 / s, w1 = e1 / s;

        float old0 = w0, old1 = w1;
        float wc0 = clip01(w0), wc1 = clip01(w1);
        bool done = false;

        for (int it = 0; it < 50; ++it) {
            float leftover = wsum((old0 - wc0) + (old1 - wc1));
            bool m0 = (wc0 != 0.1f), m1 = (wc1 != 0.1f);
            float n0 = m0 ? wc0 : 0.0f;
            float n1 = m1 ? wc1 : 0.0f;
            float denom = wsum(n0 + n1);
            float dd = (denom == 0.0f) ? 1.0f : denom;
            float wn0 = m0 ? wc0 + leftover * n0 / dd : wc0;
            float wn1 = m1 ? wc1 + leftover * n1 / dd : wc1;
            bool over = __any_sync(0xffffffffu, (wn0 > 0.1f) || (wn1 > 0.1f));
            bool ndone = !over;
            float wx0 = ndone ? wn0 : clip01(wn0);
            float wx1 = ndone ? wn1 : clip01(wn1);
            if (!done) { old0 = wn0; old1 = wn1; wc0 = wx0; wc1 = wx1; }
            done = done || ndone;
        }

        out[(size_t)b * OO + tid] = wc0;
        if (has1) out[(size_t)b * OO + tid + 32] = wc1;
    }
}

// ---------------------------------------------------------------------------
// Launch (graph-capturable: kernel launches only)
// ---------------------------------------------------------------------------
extern "C" void kernel_launch(void* const* d_in, const int* in_sizes, int n_in,
                              void* d_out, int out_size)
{
    const float* x    = (const float*)d_in[0];
    const float* W0   = (const float*)d_in[1];
    const float* U0   = (const float*)d_in[2];
    const float* b0   = (const float*)d_in[3];
    const float* W1   = (const float*)d_in[4];
    const float* U1   = (const float*)d_in[5];
    const float* b1   = (const float*)d_in[6];
    const float* Wout = (const float*)d_in[7];
    const float* bout = (const float*)d_in[8];
    float* out = (float*)d_out;

    float* p_xz = nullptr;
    __half *p_axh, *p_axl, *p_w0th, *p_w0tl, *p_w1th, *p_w1tl, *p_h0h, *p_h0l;
    cudaGetSymbolAddress((void**)&p_xz,   g_xz);
    cudaGetSymbolAddress((void**)&p_axh,  g_axh);
    cudaGetSymbolAddress((void**)&p_axl,  g_axl);
    cudaGetSymbolAddress((void**)&p_w0th, g_w0th);
    cudaGetSymbolAddress((void**)&p_w0tl, g_w0tl);
    cudaGetSymbolAddress((void**)&p_w1th, g_w1th);
    cudaGetSymbolAddress((void**)&p_w1tl, g_w1tl);
    cudaGetSymbolAddress((void**)&p_h0h,  g_h0h);
    cudaGetSymbolAddress((void**)&p_h0l,  g_h0l);

    const int REC_SMEM  = 108544;  // U hi/lo (67584) + 4-slot cp.async ring (40960)
    const int GEMM_SMEM = 3 * GSTG; // 92160
    cudaFuncSetAttribute(lstm_rec_tc, cudaFuncAttributeMaxDynamicSharedMemorySize, REC_SMEM);
    cudaFuncSetAttribute(gemm_f16<true>,  cudaFuncAttributeMaxDynamicSharedMemorySize, GEMM_SMEM);
    cudaFuncSetAttribute(gemm_f16<false>, cudaFuncAttributeMaxDynamicSharedMemorySize, GEMM_SMEM);

    dim3 gg(GG / 64, (BATCH * TT) / 128);   // (16, 2048)

    // Prep: split x; transpose+split W0, W1
    split_x_kernel<<<(int)(((size_t)BATCH * TT * FF / 2) / 256), 256>>>(x);
    split_wt_kernel<<<(1024 * 128) / 256, 256>>>(W0, 128, p_w0th, p_w0tl);
    split_wt_kernel<<<(1024 * 256) / 256, 256>>>(W1, 256, p_w1th, p_w1tl);

    // Layer 0 input projection: xz0[t][b][g]
    gemm_f16<true><<<gg, 256, GEMM_SMEM>>>(p_axh, p_axl, p_w0th, p_w0tl, b0, p_xz, FF);
    // Layer 0 recurrence -> pre-split h0seq planes
    lstm_rec_tc<<<256, 256, REC_SMEM>>>(p_xz, U0, p_h0h, p_h0l);
    // Layer 1 input projection (A = presplit h0seq planes)
    gemm_f16<false><<<gg, 256, GEMM_SMEM>>>(p_h0h, p_h0l, p_w1th, p_w1tl, b1, p_xz, HH);
    // Layer 1 recurrence (final h ends in g_hbh/g_hbl[0])
    lstm_rec_tc<<<256, 256, REC_SMEM>>>(p_xz, U1, nullptr, nullptr);
    // Head: logits -> softmax -> rebalance
    head_kernel<<<BATCH, 64>>>(Wout, bout, out);
}